// round 10
// baseline (speedup 1.0000x reference)
#include <cuda_runtime.h>
#include <cstdint>

// Problem constants
#define K_NODES 100000
#define K_RELS  500
#define K_MEM   512
#define K_IN    1024
#define K_BATCH 65536

// GEMM tiling: CTA 64x128, warp m32n32, 3 CTAs/SM
#define BM 64
#define BN 128
#define BK 32
#define STR 36                        // floats/row (144 B) — ldmatrix conflict-free
#define A_TILE (BM * STR)             // 2304 floats
#define B_TILE (BN * STR)             // 4608 floats
#define STAGE_FLOATS (A_TILE + B_TILE)
#define STAGE_BYTES (STAGE_FLOATS * 4)        // 27648
#define SMEM_BYTES (2 * STAGE_BYTES)          // 55296 (double buffer)
#define NIT (K_IN / BK)               // 32 k-chunks

// Pre-converted (tf32) weights scratch: [2][512][1024] = 4 MB
__device__ uint32_t g_Wc[2 * K_MEM * K_IN];

__device__ __forceinline__ int decode_time(const void* p) {
    int i = *(const int*)p;
    if (i < 0 || i > 1000000) i = (int)__int_as_float(i);
    return i;
}
__device__ __forceinline__ uint32_t f2tf(float f) {
    uint32_t u;
    asm("cvt.rna.tf32.f32 %0, %1;" : "=r"(u) : "f"(f));
    return u;
}

// ---------------------------------------------------------------------------
// Kernel 0: convert W_node / W_rel to tf32 bits in g_Wc
// ---------------------------------------------------------------------------
__global__ void conv_w_kernel(const float* __restrict__ Wn,
                              const float* __restrict__ Wr) {
    const int i = blockIdx.x * blockDim.x + threadIdx.x;     // float4 index
    const float4 v = ((const float4*)(blockIdx.y ? Wr : Wn))[i];
    uint4 o;
    o.x = f2tf(v.x); o.y = f2tf(v.y); o.z = f2tf(v.z); o.w = f2tf(v.w);
    ((uint4*)(g_Wc + (size_t)blockIdx.y * K_MEM * K_IN))[i] = o;
}

// ---------------------------------------------------------------------------
// Kernel 1: out[concat(entity, rel)] = memory * (t/(t+1) if t>1 else 1)
// ---------------------------------------------------------------------------
__global__ void init_out_kernel(const float* __restrict__ ent,
                                const float* __restrict__ rel,
                                const void* __restrict__ tp,
                                float* __restrict__ out) {
    const int t = decode_time(tp);
    const float s = (t > 1) ? (float)t / (float)(t + 1) : 1.0f;
    const long nent = (long)K_NODES * K_MEM;
    const long ntot = nent + (long)K_RELS * K_MEM;
    long i = ((long)blockIdx.x * blockDim.x + threadIdx.x) * 4;
    const long stride = (long)gridDim.x * blockDim.x * 4;
    for (; i < ntot; i += stride) {
        const float4 v = (i < nent) ? *(const float4*)(ent + i)
                                    : *(const float4*)(rel + (i - nent));
        float4 o;
        o.x = v.x * s; o.y = v.y * s; o.z = v.z * s; o.w = v.w * s;
        *(float4*)(out + i) = o;
    }
}

// ---------------------------------------------------------------------------
// Kernel 2: C = X @ W^T (+bias), scaled by 1/(t+1), scatter-added into out.
// tf32 mma.sync; warp tile m32n32 (32 accs) -> 3 CTAs/SM, 24 warps for
// latency hiding. A fragments ldmatrix+cvt.rna; B ldmatrix of tf32 bits.
// Double-buffered cp.async. grid = (MEM/BN, BATCH/BM, 2), col tiles fastest.
// ---------------------------------------------------------------------------
__device__ __forceinline__ void cp16(void* smem_dst, const void* gsrc) {
    uint32_t d = (uint32_t)__cvta_generic_to_shared(smem_dst);
    asm volatile("cp.async.cg.shared.global [%0], [%1], 16;" :: "r"(d), "l"(gsrc));
}
__device__ __forceinline__ void ldsm4(uint32_t& r0, uint32_t& r1,
                                      uint32_t& r2, uint32_t& r3, uint32_t a) {
    asm volatile("ldmatrix.sync.aligned.m8n8.x4.shared.b16 {%0,%1,%2,%3}, [%4];"
                 : "=r"(r0), "=r"(r1), "=r"(r2), "=r"(r3) : "r"(a));
}

__global__ __launch_bounds__(256, 3) void gemm_scatter_kernel(
    const float* __restrict__ Xn, const float* __restrict__ Xr,
    const float* __restrict__ bn, const float* __restrict__ br,
    const int* __restrict__ idn, const int* __restrict__ idr,
    const void* __restrict__ tp, float* __restrict__ out)
{
    extern __shared__ float smem[];   // 2 stages of [A | B]

    const int z = blockIdx.z;
    const float*    __restrict__ X    = z ? Xr : Xn;
    const uint32_t* __restrict__ W    = g_Wc + (size_t)z * K_MEM * K_IN;
    const float*    __restrict__ bias = z ? br : bn;
    const int*      __restrict__ ids  = z ? idr : idn;
    const int obase = z ? K_NODES : 0;

    const int t = decode_time(tp);
    const float inv = 1.0f / (float)(t + 1);

    const int bm    = blockIdx.y * BM;
    const int bnoff = blockIdx.x * BN;
    const int tid  = threadIdx.x;
    const int wid  = tid >> 5, lane = tid & 31;
    const int wm = (wid & 1) * 32;        // 2 warp rows  (m64)
    const int wn = (wid >> 1) * 32;       // 4 warp cols  (n128)
    const int grp = lane >> 2, tig = lane & 3;

    // ldmatrix per-lane offsets (bytes) — mapping validated in R6
    const uint32_t aoff =
        ((((lane & 7) + ((lane >> 3) & 1) * 8) * STR) + ((lane >> 4) & 1) * 4) * 4;
    const uint32_t boff =
        ((((lane & 7) + ((lane >> 4) & 1) * 8) * STR) + ((lane >> 3) & 1) * 4) * 4;

    const uint32_t smem0 = (uint32_t)__cvta_generic_to_shared(smem);
    const uint32_t aBase0 = smem0 + (uint32_t)(wm * STR * 4) + aoff;
    const uint32_t bBase0 = smem0 + (uint32_t)(A_TILE * 4) + (uint32_t)(wn * STR * 4) + boff;

    // Incremental fill pointers: thread covers row tid>>3 (+i*32), 16B chunk tid&7
    const char* gA = (const char*)(X + (size_t)(bm    + (tid >> 3)) * K_IN + ((tid & 7) << 2));
    const char* gB = (const char*)(W + (size_t)(bnoff + (tid >> 3)) * K_IN + ((tid & 7) << 2));
    const int sdst = (tid >> 3) * STR + ((tid & 7) << 2);

    auto fill = [&](int buf) {
        float* dA = smem + buf * STAGE_FLOATS + sdst;
        float* dB = dA + A_TILE;
        #pragma unroll
        for (int i = 0; i < 2; i++)                       // A: 64 rows
            cp16(dA + i * 32 * STR, gA + (size_t)i * 32 * K_IN * 4);
        #pragma unroll
        for (int i = 0; i < 4; i++)                       // B: 128 rows
            cp16(dB + i * 32 * STR, gB + (size_t)i * 32 * K_IN * 4);
        asm volatile("cp.async.commit_group;");
        gA += BK * 4;
        gB += BK * 4;
    };

    float acc[2][4][4] = {};   // 32 accumulators (m32 x n32)

    fill(0); fill(1);

    for (int it = 0; it < NIT; ++it) {
        asm volatile("cp.async.wait_group 1;");
        __syncthreads();

        const uint32_t aB = aBase0 + (it & 1) * STAGE_BYTES;
        const uint32_t bB = bBase0 + (it & 1) * STAGE_BYTES;

        #pragma unroll
        for (int ks = 0; ks < 4; ++ks) {
            uint32_t af[2][4], bf[4][2];
            #pragma unroll
            for (int mt = 0; mt < 2; ++mt) {
                uint32_t r0, r1, r2, r3;
                ldsm4(r0, r1, r2, r3, aB + mt * (16 * STR * 4) + ks * 32);
                af[mt][0] = f2tf(__uint_as_float(r0));
                af[mt][1] = f2tf(__uint_as_float(r1));
                af[mt][2] = f2tf(__uint_as_float(r2));
                af[mt][3] = f2tf(__uint_as_float(r3));
            }
            #pragma unroll
            for (int np = 0; np < 2; ++np) {
                uint32_t r0, r1, r2, r3;
                ldsm4(r0, r1, r2, r3, bB + np * (16 * STR * 4) + ks * 32);
                bf[2 * np][0]     = r0;        // already tf32 bits
                bf[2 * np][1]     = r1;
                bf[2 * np + 1][0] = r2;
                bf[2 * np + 1][1] = r3;
            }
            #pragma unroll
            for (int mt = 0; mt < 2; ++mt)
                #pragma unroll
                for (int nt = 0; nt < 4; ++nt)
                    asm volatile(
                        "mma.sync.aligned.m16n8k8.row.col.f32.tf32.tf32.f32 "
                        "{%0,%1,%2,%3}, {%4,%5,%6,%7}, {%8,%9}, {%0,%1,%2,%3};"
                        : "+f"(acc[mt][nt][0]), "+f"(acc[mt][nt][1]),
                          "+f"(acc[mt][nt][2]), "+f"(acc[mt][nt][3])
                        : "r"(af[mt][0]), "r"(af[mt][1]), "r"(af[mt][2]), "r"(af[mt][3]),
                          "r"(bf[nt][0]), "r"(bf[nt][1]));
        }

        __syncthreads();
        if (it + 2 < NIT) fill(it & 1);
        else asm volatile("cp.async.commit_group;");   // keep group count stable
    }

    // Epilogue: (acc + bias) * inv, scatter-add via float2 vector atomics
    float2 bv[4];
    #pragma unroll
    for (int nt = 0; nt < 4; ++nt) {
        int col = bnoff + wn + nt * 8 + tig * 2;
        bv[nt].x = bias[col];
        bv[nt].y = bias[col + 1];
    }
    #pragma unroll
    for (int mt = 0; mt < 2; ++mt) {
        #pragma unroll
        for (int h = 0; h < 2; ++h) {
            const int gb = bm + wm + mt * 16 + grp + h * 8;
            const long orow = (long)(ids[gb] + obase);
            float* dst = out + orow * K_MEM;
            #pragma unroll
            for (int nt = 0; nt < 4; ++nt) {
                const int col = bnoff + wn + nt * 8 + tig * 2;
                float2 v;
                v.x = (acc[mt][nt][h * 2 + 0] + bv[nt].x) * inv;
                v.y = (acc[mt][nt][h * 2 + 1] + bv[nt].y) * inv;
                atomicAdd((float2*)(dst + col), v);
            }
        }
    }
}

// ---------------------------------------------------------------------------
extern "C" void kernel_launch(void* const* d_in, const int* in_sizes, int n_in,
                              void* d_out, int out_size) {
    const float* Xn  = (const float*)d_in[0];
    const float* Xr  = (const float*)d_in[1];
    const int*   idn = (const int*)  d_in[2];
    const int*   idr = (const int*)  d_in[3];
    const float* ent = (const float*)d_in[4];
    const float* rel = (const float*)d_in[5];
    const float* Wn  = (const float*)d_in[6];
    const float* bn  = (const float*)d_in[7];
    const float* Wr  = (const float*)d_in[8];
    const float* br  = (const float*)d_in[9];
    const void*  tp  = d_in[10];
    float* out = (float*)d_out;

    // 0) W -> tf32 scratch
    conv_w_kernel<<<dim3(K_MEM * K_IN / 4 / 256, 2), 256>>>(Wn, Wr);

    // 1) out = scaled memory state
    init_out_kernel<<<1184, 256>>>(ent, rel, tp, out);

    // 2) GEMM + scatter-add
    cudaFuncSetAttribute(gemm_scatter_kernel,
                         cudaFuncAttributeMaxDynamicSharedMemorySize, SMEM_BYTES);
    dim3 grid(K_MEM / BN, K_BATCH / BM, 2);
    gemm_scatter_kernel<<<grid, 256, SMEM_BYTES>>>(
        Xn, Xr, bn, br, idn, idr, tp, out);
}

// round 12
// speedup vs baseline: 1.0048x; 1.0048x over previous
#include <cuda_runtime.h>
#include <cstdint>

// Problem constants
#define K_NODES 100000
#define K_RELS  500
#define K_MEM   512
#define K_IN    1024
#define K_BATCH 65536

// GEMM tiling (R9 structure, persistent CTAs)
#define BM 128
#define BN 128
#define BK 32
#define STR 36                       // floats/row (144 B) — ldmatrix conflict-free
#define A_TILE (BM * STR)            // 4608 floats
#define B_TILE (BN * STR)            // 4608 floats
#define STAGE_FLOATS (A_TILE + B_TILE)
#define STAGE_BYTES (STAGE_FLOATS * 4)       // 36864
#define NSTAGE 3
#define SMEM_BYTES (NSTAGE * STAGE_BYTES)    // 110592
#define CHUNKS_PER_TILE (K_IN / BK)  // 32
#define N_TILES 4096                 // 4 bx * 512 by * 2 z
#define GRID_P 296                   // 2 CTAs x 148 SMs

// Pre-converted (tf32) weights scratch: [2][512][1024] = 4 MB
__device__ uint32_t g_Wc[2 * K_MEM * K_IN];

__device__ __forceinline__ int decode_time(const void* p) {
    int i = *(const int*)p;
    if (i < 0 || i > 1000000) i = (int)__int_as_float(i);
    return i;
}
__device__ __forceinline__ uint32_t f2tf(float f) {
    uint32_t u;
    asm("cvt.rna.tf32.f32 %0, %1;" : "=r"(u) : "f"(f));
    return u;
}

// ---------------------------------------------------------------------------
// Kernel 0: convert W_node / W_rel to tf32 bits in g_Wc
// ---------------------------------------------------------------------------
__global__ void conv_w_kernel(const float* __restrict__ Wn,
                              const float* __restrict__ Wr) {
    const int i = blockIdx.x * blockDim.x + threadIdx.x;     // float4 index
    const float4 v = ((const float4*)(blockIdx.y ? Wr : Wn))[i];
    uint4 o;
    o.x = f2tf(v.x); o.y = f2tf(v.y); o.z = f2tf(v.z); o.w = f2tf(v.w);
    ((uint4*)(g_Wc + (size_t)blockIdx.y * K_MEM * K_IN))[i] = o;
}

// ---------------------------------------------------------------------------
// Kernel 1: out[concat(entity, rel)] = memory * (t/(t+1) if t>1 else 1)
// ---------------------------------------------------------------------------
__global__ void init_out_kernel(const float* __restrict__ ent,
                                const float* __restrict__ rel,
                                const void* __restrict__ tp,
                                float* __restrict__ out) {
    const int t = decode_time(tp);
    const float s = (t > 1) ? (float)t / (float)(t + 1) : 1.0f;
    const long nent = (long)K_NODES * K_MEM;
    const long ntot = nent + (long)K_RELS * K_MEM;
    long i = ((long)blockIdx.x * blockDim.x + threadIdx.x) * 4;
    const long stride = (long)gridDim.x * blockDim.x * 4;
    for (; i < ntot; i += stride) {
        const float4 v = (i < nent) ? *(const float4*)(ent + i)
                                    : *(const float4*)(rel + (i - nent));
        float4 o;
        o.x = v.x * s; o.y = v.y * s; o.z = v.z * s; o.w = v.w * s;
        *(float4*)(out + i) = o;
    }
}

// ---------------------------------------------------------------------------
// Kernel 2 (persistent): each CTA loops over tiles; flat chunk pipeline runs
// across tile boundaries so epilogue atomics + next tile's fills overlap.
// Mainloop identical to R9: tf32 mma.sync, A ldmatrix+cvt.rna, B ldmatrix of
// pre-converted tf32 bits, 3-stage cp.async ring, one barrier per chunk.
// ---------------------------------------------------------------------------
__device__ __forceinline__ void cp16(void* smem_dst, const void* gsrc) {
    uint32_t d = (uint32_t)__cvta_generic_to_shared(smem_dst);
    asm volatile("cp.async.cg.shared.global [%0], [%1], 16;" :: "r"(d), "l"(gsrc));
}
__device__ __forceinline__ void ldsm4(uint32_t& r0, uint32_t& r1,
                                      uint32_t& r2, uint32_t& r3, uint32_t a) {
    asm volatile("ldmatrix.sync.aligned.m8n8.x4.shared.b16 {%0,%1,%2,%3}, [%4];"
                 : "=r"(r0), "=r"(r1), "=r"(r2), "=r"(r3) : "r"(a));
}

__global__ __launch_bounds__(256, 2) void gemm_scatter_kernel(
    const float* __restrict__ Xn, const float* __restrict__ Xr,
    const float* __restrict__ bn, const float* __restrict__ br,
    const int* __restrict__ idn, const int* __restrict__ idr,
    const void* __restrict__ tp, float* __restrict__ out)
{
    extern __shared__ float smem[];   // 3 stages of [A | B]

    const int bid = blockIdx.x;
    const int t = decode_time(tp);
    const float inv = 1.0f / (float)(t + 1);

    const int tid  = threadIdx.x;
    const int wid  = tid >> 5, lane = tid & 31;
    const int wm = (wid & 1) * 64;
    const int wn = (wid >> 1) * 32;
    const int grp = lane >> 2, tig = lane & 3;

    // ldmatrix per-lane offsets (bytes) — mapping validated in R6
    const uint32_t aoff =
        ((((lane & 7) + ((lane >> 3) & 1) * 8) * STR) + ((lane >> 4) & 1) * 4) * 4;
    const uint32_t boff =
        ((((lane & 7) + ((lane >> 4) & 1) * 8) * STR) + ((lane >> 3) & 1) * 4) * 4;

    const uint32_t smem0 = (uint32_t)__cvta_generic_to_shared(smem);
    const uint32_t aBase0 = smem0 + (uint32_t)(wm * STR * 4) + aoff;
    const uint32_t bBase0 = smem0 + (uint32_t)(A_TILE * 4) + (uint32_t)(wn * STR * 4) + boff;

    // Per-CTA tile count (tiles j: tau = bid + j*GRID_P < N_TILES)
    const int nt_local = (N_TILES - bid + GRID_P - 1) / GRID_P;
    const int total_chunks = nt_local * CHUNKS_PER_TILE;

    // Fill-side pointer state (advanced per chunk, re-seeded per tile)
    const char* gA = nullptr;
    const char* gB = nullptr;
    const int frow = tid >> 3;                 // fill row within 32-row group
    const int fcol = (tid & 7) << 2;           // fill col (floats)
    const int sdst = frow * STR + fcol;

    auto fill = [&](int f) {
        if ((f & 31) == 0) {                   // entering a new tile: re-seed
            const int j   = f >> 5;
            const int tau = bid + j * GRID_P;
            const int z   = tau >> 11;
            const int bm    = ((tau >> 2) & 511) * BM;
            const int bnoff = (tau & 3) * BN;
            const float*    X = z ? Xr : Xn;
            const uint32_t* W = g_Wc + (size_t)z * K_MEM * K_IN;
            gA = (const char*)(X + (size_t)(bm    + frow) * K_IN + fcol);
            gB = (const char*)(W + (size_t)(bnoff + frow) * K_IN + fcol);
        }
        float* dA = smem + (f % 3) * STAGE_FLOATS + sdst;
        float* dB = dA + A_TILE;
        #pragma unroll
        for (int i = 0; i < 4; i++)
            cp16(dA + i * 32 * STR, gA + (size_t)i * 32 * K_IN * 4);
        #pragma unroll
        for (int i = 0; i < 4; i++)
            cp16(dB + i * 32 * STR, gB + (size_t)i * 32 * K_IN * 4);
        asm volatile("cp.async.commit_group;");
        gA += BK * 4;
        gB += BK * 4;
    };

    float acc[4][4][4] = {};   // 64 accumulators (m64 x n32)

    fill(0); fill(1);

    for (int c = 0; c < total_chunks; ++c) {
        asm volatile("cp.async.wait_group 1;");
        __syncthreads();                        // single barrier per chunk

        const int f = c + 2;
        if (f < total_chunks) fill(f);
        else asm volatile("cp.async.commit_group;");

        const uint32_t aB = aBase0 + (c % 3) * STAGE_BYTES;
        const uint32_t bB = bBase0 + (c % 3) * STAGE_BYTES;

        #pragma unroll
        for (int ks = 0; ks < 4; ++ks) {
            uint32_t af[4][4], bf[4][2];
            #pragma unroll
            for (int mt = 0; mt < 4; ++mt) {
                uint32_t r0, r1, r2, r3;
                ldsm4(r0, r1, r2, r3, aB + mt * (16 * STR * 4) + ks * 32);
                af[mt][0] = f2tf(__uint_as_float(r0));
                af[mt][1] = f2tf(__uint_as_float(r1));
                af[mt][2] = f2tf(__uint_as_float(r2));
                af[mt][3] = f2tf(__uint_as_float(r3));
            }
            #pragma unroll
            for (int np = 0; np < 2; ++np) {
                uint32_t r0, r1, r2, r3;
                ldsm4(r0, r1, r2, r3, bB + np * (16 * STR * 4) + ks * 32);
                bf[2 * np][0]     = r0;        // already tf32 bits
                bf[2 * np][1]     = r1;
                bf[2 * np + 1][0] = r2;
                bf[2 * np + 1][1] = r3;
            }
            #pragma unroll
            for (int mt = 0; mt < 4; ++mt)
                #pragma unroll
                for (int nt = 0; nt < 4; ++nt)
                    asm volatile(
                        "mma.sync.aligned.m16n8k8.row.col.f32.tf32.tf32.f32 "
                        "{%0,%1,%2,%3}, {%4,%5,%6,%7}, {%8,%9}, {%0,%1,%2,%3};"
                        : "+f"(acc[mt][nt][0]), "+f"(acc[mt][nt][1]),
                          "+f"(acc[mt][nt][2]), "+f"(acc[mt][nt][3])
                        : "r"(af[mt][0]), "r"(af[mt][1]), "r"(af[mt][2]), "r"(af[mt][3]),
                          "r"(bf[nt][0]), "r"(bf[nt][1]));
        }

        // Tile finished: epilogue (overlaps DMA of next tile already in flight)
        if ((c & 31) == 31) {
            const int j   = c >> 5;
            const int tau = bid + j * GRID_P;
            const int z   = tau >> 11;
            const int bm    = ((tau >> 2) & 511) * BM;
            const int bnoff = (tau & 3) * BN;
            const float* bias = z ? br : bn;
            const int*   ids  = z ? idr : idn;
            const int obase = z ? K_NODES : 0;

            #pragma unroll
            for (int mt = 0; mt < 4; ++mt) {
                #pragma unroll
                for (int h = 0; h < 2; ++h) {
                    const int gb = bm + wm + mt * 16 + grp + h * 8;
                    const long orow = (long)(ids[gb] + obase);
                    float* dst = out + orow * K_MEM;
                    #pragma unroll
                    for (int nt = 0; nt < 4; ++nt) {
                        const int col = bnoff + wn + nt * 8 + tig * 2;
                        float2 v;
                        v.x = (acc[mt][nt][h * 2 + 0] + __ldg(bias + col))     * inv;
                        v.y = (acc[mt][nt][h * 2 + 1] + __ldg(bias + col + 1)) * inv;
                        atomicAdd((float2*)(dst + col), v);
                    }
                }
            }
            #pragma unroll
            for (int mt = 0; mt < 4; ++mt)
                #pragma unroll
                for (int nt = 0; nt < 4; ++nt)
                    #pragma unroll
                    for (int q = 0; q < 4; ++q)
                        acc[mt][nt][q] = 0.0f;
        }
    }
}

// ---------------------------------------------------------------------------
extern "C" void kernel_launch(void* const* d_in, const int* in_sizes, int n_in,
                              void* d_out, int out_size) {
    const float* Xn  = (const float*)d_in[0];
    const float* Xr  = (const float*)d_in[1];
    const int*   idn = (const int*)  d_in[2];
    const int*   idr = (const int*)  d_in[3];
    const float* ent = (const float*)d_in[4];
    const float* rel = (const float*)d_in[5];
    const float* Wn  = (const float*)d_in[6];
    const float* bn  = (const float*)d_in[7];
    const float* Wr  = (const float*)d_in[8];
    const float* br  = (const float*)d_in[9];
    const void*  tp  = d_in[10];
    float* out = (float*)d_out;

    // 0) W -> tf32 scratch
    conv_w_kernel<<<dim3(K_MEM * K_IN / 4 / 256, 2), 256>>>(Wn, Wr);

    // 1) out = scaled memory state
    init_out_kernel<<<1184, 256>>>(ent, rel, tp, out);

    // 2) Persistent GEMM + scatter-add
    cudaFuncSetAttribute(gemm_scatter_kernel,
                         cudaFuncAttributeMaxDynamicSharedMemorySize, SMEM_BYTES);
    gemm_scatter_kernel<<<GRID_P, 256, SMEM_BYTES>>>(
        Xn, Xr, bn, br, idn, idr, tp, out);
}

// round 13
// speedup vs baseline: 1.6127x; 1.6050x over previous
#include <cuda_runtime.h>
#include <cuda_fp16.h>
#include <cstdint>

// Problem constants
#define K_NODES 100000
#define K_RELS  500
#define K_MEM   512
#define K_IN    1024
#define K_BATCH 65536

// GEMM tiling (R9 structure, fp16 operands, BK=64)
#define BM 128
#define BN 128
#define BK 64                         // halves per k-chunk (= 128 B/row)
#define STR_H 72                      // halves/row (144 B) — ldmatrix conflict-free
#define A_TILE_H (BM * STR_H)         // 9216 halves
#define B_TILE_H (BN * STR_H)         // 9216 halves
#define STAGE_H (A_TILE_H + B_TILE_H) // halves per stage
#define STAGE_BYTES (STAGE_H * 2)     // 36864
#define NSTAGE 3
#define SMEM_BYTES (NSTAGE * STAGE_BYTES)   // 110592
#define NIT (K_IN / BK)               // 16 k-chunks

// fp16 scratch: X [2][65536][1024] halves = 256 MB, W [2][512][1024] = 2 MB
__device__ uint32_t g_Xh[(size_t)2 * K_BATCH * K_IN / 2];
__device__ uint32_t g_Wh[(size_t)2 * K_MEM * K_IN / 2];

__device__ __forceinline__ int decode_time(const void* p) {
    int i = *(const int*)p;
    if (i < 0 || i > 1000000) i = (int)__int_as_float(i);
    return i;
}

// ---------------------------------------------------------------------------
// Kernel 0a/0b: convert X / W to fp16
// ---------------------------------------------------------------------------
__global__ void conv_x_kernel(const float* __restrict__ Xn,
                              const float* __restrict__ Xr) {
    const size_t i = (size_t)blockIdx.x * blockDim.x + threadIdx.x;  // float4 idx
    const float4 v = ((const float4*)(blockIdx.y ? Xr : Xn))[i];
    __half2 lo = __floats2half2_rn(v.x, v.y);
    __half2 hi = __floats2half2_rn(v.z, v.w);
    uint2 o;
    o.x = *(uint32_t*)&lo;
    o.y = *(uint32_t*)&hi;
    ((uint2*)(g_Xh + (size_t)blockIdx.y * K_BATCH * K_IN / 2))[i] = o;
}
__global__ void conv_w_kernel(const float* __restrict__ Wn,
                              const float* __restrict__ Wr) {
    const size_t i = (size_t)blockIdx.x * blockDim.x + threadIdx.x;
    const float4 v = ((const float4*)(blockIdx.y ? Wr : Wn))[i];
    __half2 lo = __floats2half2_rn(v.x, v.y);
    __half2 hi = __floats2half2_rn(v.z, v.w);
    uint2 o;
    o.x = *(uint32_t*)&lo;
    o.y = *(uint32_t*)&hi;
    ((uint2*)(g_Wh + (size_t)blockIdx.y * K_MEM * K_IN / 2))[i] = o;
}

// ---------------------------------------------------------------------------
// Kernel 1: out[concat(entity, rel)] = memory * (t/(t+1) if t>1 else 1)
// ---------------------------------------------------------------------------
__global__ void init_out_kernel(const float* __restrict__ ent,
                                const float* __restrict__ rel,
                                const void* __restrict__ tp,
                                float* __restrict__ out) {
    const int t = decode_time(tp);
    const float s = (t > 1) ? (float)t / (float)(t + 1) : 1.0f;
    const long nent = (long)K_NODES * K_MEM;
    const long ntot = nent + (long)K_RELS * K_MEM;
    long i = ((long)blockIdx.x * blockDim.x + threadIdx.x) * 4;
    const long stride = (long)gridDim.x * blockDim.x * 4;
    for (; i < ntot; i += stride) {
        const float4 v = (i < nent) ? *(const float4*)(ent + i)
                                    : *(const float4*)(rel + (i - nent));
        float4 o;
        o.x = v.x * s; o.y = v.y * s; o.z = v.z * s; o.w = v.w * s;
        *(float4*)(out + i) = o;
    }
}

// ---------------------------------------------------------------------------
// Kernel 2: C = X @ W^T (+bias), scaled, scatter-added. fp16 mma m16n8k16,
// fp32 accumulate. Structure identical to the validated tf32 R9 kernel:
// ldmatrix fragments, 3-stage cp.async ring, one barrier per chunk,
// grid = (MEM/BN, BATCH/BM, 2) with col tiles fastest (L2 A-reuse).
// ---------------------------------------------------------------------------
__device__ __forceinline__ void cp16(void* smem_dst, const void* gsrc) {
    uint32_t d = (uint32_t)__cvta_generic_to_shared(smem_dst);
    asm volatile("cp.async.cg.shared.global [%0], [%1], 16;" :: "r"(d), "l"(gsrc));
}
__device__ __forceinline__ void ldsm4(uint32_t& r0, uint32_t& r1,
                                      uint32_t& r2, uint32_t& r3, uint32_t a) {
    asm volatile("ldmatrix.sync.aligned.m8n8.x4.shared.b16 {%0,%1,%2,%3}, [%4];"
                 : "=r"(r0), "=r"(r1), "=r"(r2), "=r"(r3) : "r"(a));
}

__global__ __launch_bounds__(256, 2) void gemm_scatter_kernel(
    const float* __restrict__ bn, const float* __restrict__ br,
    const int* __restrict__ idn, const int* __restrict__ idr,
    const void* __restrict__ tp, float* __restrict__ out)
{
    extern __shared__ __half smem[];   // 3 stages of [A | B]

    const int z = blockIdx.z;
    const uint32_t* __restrict__ Xh  = g_Xh + (size_t)z * K_BATCH * K_IN / 2;
    const uint32_t* __restrict__ Wh  = g_Wh + (size_t)z * K_MEM * K_IN / 2;
    const float*    __restrict__ bias = z ? br : bn;
    const int*      __restrict__ ids  = z ? idr : idn;
    const int obase = z ? K_NODES : 0;

    const int t = decode_time(tp);
    const float inv = 1.0f / (float)(t + 1);

    const int bm    = blockIdx.y * BM;
    const int bnoff = blockIdx.x * BN;
    const int tid  = threadIdx.x;
    const int wid  = tid >> 5, lane = tid & 31;
    const int wm = (wid & 1) * 64;
    const int wn = (wid >> 1) * 32;
    const int grp = lane >> 2, tig = lane & 3;

    // ldmatrix per-lane offsets (bytes): same tile decomposition as R6/R9,
    // k-offset unit is 8 halves (16 B)
    const uint32_t aoff =
        ((((lane & 7) + ((lane >> 3) & 1) * 8) * STR_H) + ((lane >> 4) & 1) * 8) * 2;
    const uint32_t boff =
        ((((lane & 7) + ((lane >> 4) & 1) * 8) * STR_H) + ((lane >> 3) & 1) * 8) * 2;

    const uint32_t smem0 = (uint32_t)__cvta_generic_to_shared(smem);
    const uint32_t aBase0 = smem0 + (uint32_t)(wm * STR_H * 2) + aoff;
    const uint32_t bBase0 = smem0 + (uint32_t)(A_TILE_H * 2)
                          + (uint32_t)(wn * STR_H * 2) + boff;

    // Incremental fill pointers: thread covers row tid>>3 (+i*32), 16B chunk tid&7
    const char* gA = (const char*)Xh + ((size_t)(bm    + (tid >> 3)) * K_IN
                                        + ((tid & 7) << 3)) * 2;
    const char* gB = (const char*)Wh + ((size_t)(bnoff + (tid >> 3)) * K_IN
                                        + ((tid & 7) << 3)) * 2;
    const int sdst = (tid >> 3) * STR_H + ((tid & 7) << 3);   // halves

    auto fill = [&](int st) {
        __half* dA = smem + st * STAGE_H + sdst;
        __half* dB = dA + A_TILE_H;
        #pragma unroll
        for (int i = 0; i < 4; i++)
            cp16(dA + i * 32 * STR_H, gA + (size_t)i * 32 * K_IN * 2);
        #pragma unroll
        for (int i = 0; i < 4; i++)
            cp16(dB + i * 32 * STR_H, gB + (size_t)i * 32 * K_IN * 2);
        asm volatile("cp.async.commit_group;");
        gA += BK * 2;
        gB += BK * 2;
    };

    float acc[4][4][4] = {};   // 64 accumulators (m64 x n32)

    fill(0); fill(1);

    for (int it = 0; it < NIT; ++it) {
        const int st = it % 3;
        asm volatile("cp.async.wait_group 1;");
        __syncthreads();                       // single barrier per chunk

        // Refill stage 2 ahead (ring: never the stage being read now or next)
        if (it + 2 < NIT) fill((it + 2) % 3);
        else asm volatile("cp.async.commit_group;");

        const uint32_t aB = aBase0 + st * STAGE_BYTES;
        const uint32_t bB = bBase0 + st * STAGE_BYTES;

        #pragma unroll
        for (int ks = 0; ks < 4; ++ks) {       // 4 x k16 per chunk
            uint32_t af[4][4], bf[4][2];
            #pragma unroll
            for (int mt = 0; mt < 4; ++mt) {
                ldsm4(af[mt][0], af[mt][1], af[mt][2], af[mt][3],
                      aB + mt * (16 * STR_H * 2) + ks * 32);
            }
            #pragma unroll
            for (int np = 0; np < 2; ++np) {
                uint32_t r0, r1, r2, r3;
                ldsm4(r0, r1, r2, r3, bB + np * (16 * STR_H * 2) + ks * 32);
                bf[2 * np][0]     = r0;        // n-tile 2np,   k0-7
                bf[2 * np][1]     = r1;        // n-tile 2np,   k8-15
                bf[2 * np + 1][0] = r2;        // n-tile 2np+1, k0-7
                bf[2 * np + 1][1] = r3;        // n-tile 2np+1, k8-15
            }
            #pragma unroll
            for (int mt = 0; mt < 4; ++mt)
                #pragma unroll
                for (int nt = 0; nt < 4; ++nt)
                    asm volatile(
                        "mma.sync.aligned.m16n8k16.row.col.f32.f16.f16.f32 "
                        "{%0,%1,%2,%3}, {%4,%5,%6,%7}, {%8,%9}, {%0,%1,%2,%3};"
                        : "+f"(acc[mt][nt][0]), "+f"(acc[mt][nt][1]),
                          "+f"(acc[mt][nt][2]), "+f"(acc[mt][nt][3])
                        : "r"(af[mt][0]), "r"(af[mt][1]), "r"(af[mt][2]), "r"(af[mt][3]),
                          "r"(bf[nt][0]), "r"(bf[nt][1]));
        }
    }

    // Epilogue: (acc + bias) * inv, scatter-add via float2 vector atomics
    float2 bv[4];
    #pragma unroll
    for (int nt = 0; nt < 4; ++nt) {
        int col = bnoff + wn + nt * 8 + tig * 2;
        bv[nt].x = bias[col];
        bv[nt].y = bias[col + 1];
    }
    #pragma unroll
    for (int mt = 0; mt < 4; ++mt) {
        #pragma unroll
        for (int h = 0; h < 2; ++h) {
            const int gb = bm + wm + mt * 16 + grp + h * 8;
            const long orow = (long)(ids[gb] + obase);
            float* dst = out + orow * K_MEM;
            #pragma unroll
            for (int nt = 0; nt < 4; ++nt) {
                const int col = bnoff + wn + nt * 8 + tig * 2;
                float2 v;
                v.x = (acc[mt][nt][h * 2 + 0] + bv[nt].x) * inv;
                v.y = (acc[mt][nt][h * 2 + 1] + bv[nt].y) * inv;
                atomicAdd((float2*)(dst + col), v);
            }
        }
    }
}

// ---------------------------------------------------------------------------
extern "C" void kernel_launch(void* const* d_in, const int* in_sizes, int n_in,
                              void* d_out, int out_size) {
    const float* Xn  = (const float*)d_in[0];
    const float* Xr  = (const float*)d_in[1];
    const int*   idn = (const int*)  d_in[2];
    const int*   idr = (const int*)  d_in[3];
    const float* ent = (const float*)d_in[4];
    const float* rel = (const float*)d_in[5];
    const float* Wn  = (const float*)d_in[6];
    const float* bn  = (const float*)d_in[7];
    const float* Wr  = (const float*)d_in[8];
    const float* br  = (const float*)d_in[9];
    const void*  tp  = d_in[10];
    float* out = (float*)d_out;

    // 0) X, W -> fp16 scratch
    conv_x_kernel<<<dim3(K_BATCH * (K_IN / 4) / 256, 2), 256>>>(Xn, Xr);
    conv_w_kernel<<<dim3(K_MEM * (K_IN / 4) / 256, 2), 256>>>(Wn, Wr);

    // 1) out = scaled memory state
    init_out_kernel<<<1184, 256>>>(ent, rel, tp, out);

    // 2) GEMM + scatter-add
    cudaFuncSetAttribute(gemm_scatter_kernel,
                         cudaFuncAttributeMaxDynamicSharedMemorySize, SMEM_BYTES);
    dim3 grid(K_MEM / BN, K_BATCH / BM, 2);
    gemm_scatter_kernel<<<grid, 256, SMEM_BYTES>>>(
        bn, br, idn, idr, tp, out);
}